// round 16
// baseline (speedup 1.0000x reference)
#include <cuda_runtime.h>
#include <cuda_fp16.h>
#include <math.h>
#include <stdint.h>

// ===========================================================================
// Helpers
// ===========================================================================
__device__ __forceinline__ unsigned smem_u32(const void* p) {
    unsigned a;
    asm("{ .reg .u64 t; cvta.to.shared.u64 t, %1; cvt.u32.u64 %0, t; }"
        : "=r"(a) : "l"(p));
    return a;
}
#define CP16(dst_u32, src_ptr) \
    asm volatile("cp.async.cg.shared.global [%0], [%1], 16;" \
                 :: "r"(dst_u32), "l"(src_ptr))
#define CP_COMMIT() asm volatile("cp.async.commit_group;")
#define CP_WAIT2()  asm volatile("cp.async.wait_group 2;")
#define CP_WAIT1()  asm volatile("cp.async.wait_group 1;")
#define CP_WAIT0()  asm volatile("cp.async.wait_group 0;")

__device__ __forceinline__ void ldsm_x4(unsigned addr, unsigned& r0, unsigned& r1,
                                        unsigned& r2, unsigned& r3) {
    asm volatile("ldmatrix.sync.aligned.m8n8.x4.shared.b16 {%0,%1,%2,%3}, [%4];"
                 : "=r"(r0), "=r"(r1), "=r"(r2), "=r"(r3) : "r"(addr));
}
__device__ __forceinline__ void ldsm_x2(unsigned addr, unsigned& r0, unsigned& r1) {
    asm volatile("ldmatrix.sync.aligned.m8n8.x2.shared.b16 {%0,%1}, [%2];"
                 : "=r"(r0), "=r"(r1) : "r"(addr));
}
// fp16 MMA, fp32 accumulate
__device__ __forceinline__ void mma16816(float* d, unsigned a0, unsigned a1,
                                         unsigned a2, unsigned a3,
                                         unsigned b0, unsigned b1) {
    asm volatile("mma.sync.aligned.m16n8k16.row.col.f32.f16.f16.f32 "
                 "{%0,%1,%2,%3}, {%4,%5,%6,%7}, {%8,%9}, {%0,%1,%2,%3};"
                 : "+f"(d[0]), "+f"(d[1]), "+f"(d[2]), "+f"(d[3])
                 : "r"(a0), "r"(a1), "r"(a2), "r"(a3), "r"(b0), "r"(b1));
}
__device__ __forceinline__ void sts32(unsigned addr, unsigned v) {
    asm volatile("st.shared.b32 [%0], %1;" :: "r"(addr), "r"(v) : "memory");
}
__device__ __forceinline__ float redsum8(float v) {
    v += __shfl_xor_sync(0xffffffffu, v, 4);
    v += __shfl_xor_sync(0xffffffffu, v, 8);
    v += __shfl_xor_sync(0xffffffffu, v, 16);
    return v;
}
__device__ __forceinline__ unsigned pack_h2(float v0, float v1) {
    __half2 h = __floats2half2_rn(v0, v1);
    return *(unsigned*)&h;
}

// ===========================================================================
// Globals
// ===========================================================================
__device__ __align__(16) __half g_iph[65536 * 400];     // input_pi (fp16)
__device__ __align__(16) __half W0g[256 * 72];          // Wa0^T fp16, pitch 72
__device__ __align__(16) __half W1g[400 * 264];         // Wa1^T fp16, pitch 264
__device__ __align__(16) __half Wp0g[256 * 408];        // Wp0^T fp16, pitch 408
__device__ __align__(16) __half Wp1g[256 * 264];        // Wp1^T fp16, pitch 264
__device__ __align__(16) __half Wp2g[8 * 264];          // Wp2^T fp16, pitch 264

// ===========================================================================
// Prep: fp16 weight images (n-major, k contiguous)
// ===========================================================================
__global__ void k_prep(const float* __restrict__ Wa0, const float* __restrict__ Wa1,
                       const float* __restrict__ Wp0, const float* __restrict__ Wp1,
                       const float* __restrict__ Wp2) {
    int idx = blockIdx.x * 256 + threadIdx.x;
    if (idx < 16384) {                                   // W0: 256n x 64k
        int n = idx >> 6, k = idx & 63;
        float v = (k < 50) ? Wa0[k * 256 + n] : 0.f;
        W0g[n * 72 + k] = __float2half(v);
    } else if (idx < 118784) {                           // W1: 400n x 256k
        int t = idx - 16384;
        int k = t / 400, n = t % 400;
        W1g[n * 264 + k] = __float2half(Wa1[k * 400 + n]);
    } else if (idx < 118784 + 102400) {                  // Wp0: 256n x 400k
        int t = idx - 118784;
        int n = t & 255, k = t >> 8;
        Wp0g[n * 408 + k] = __float2half(Wp0[k * 256 + n]);
    } else if (idx < 221184 + 65536) {                   // Wp1: 256n x 256k
        int t = idx - 221184;
        int n = t & 255, k = t >> 8;
        Wp1g[n * 264 + k] = __float2half(Wp1[k * 256 + n]);
    } else if (idx < 286720 + 2048) {                    // Wp2: 8n x 256k
        int t = idx - 286720;
        int n = t & 7, k = t >> 3;
        Wp2g[n * 264 + k] = __float2half(Wp2[k * 8 + n]);
    }
}

// ===========================================================================
// Kernel 1: attention + gather + a0 + a1 + object-sum -> g_iph (B x 400 fp16)
// (unchanged from round 15)
// ===========================================================================
#define RS      21120
#define OFF_R   0
#define OFF_A0  63360
#define OFF_BA1 81792
#define OFF_BA0 83392
#define SMEM_MAIN 84416

__global__ __launch_bounds__(256, 2)
void k_main(const float* __restrict__ o,   const float* __restrict__ g,
            const float* __restrict__ Wc,  const float* __restrict__ bc,
            const float* __restrict__ ba0, const float* __restrict__ ba1)
{
    extern __shared__ __align__(1024) unsigned char smem[];
    const unsigned sbase = smem_u32(smem);
    const int tid = threadIdx.x, lane = tid & 31, warp = tid >> 5;
    const int e0 = blockIdx.x * 16;

    // ---- G_A: B0 pair0 -> slot 2 ----
    for (int q = tid; q < 1152; q += 256)
        CP16(sbase + OFF_R + 2 * RS + q * 16, (const char*)W0g + q * 16);
    CP_COMMIT();

    float* ba0_sh = (float*)(smem + OFF_BA0);
    float* ba1_sh = (float*)(smem + OFF_BA1);
    ba0_sh[tid] = ba0[tid];
    for (int i = tid; i < 400; i += 256) ba1_sh[i] = ba1[i];

    // ---- phase 0 ----
    {
        float* o_sh = (float*)(smem + 0);
        float* g_sh = (float*)(smem + 16640);
        float* att  = (float*)(smem + 23040);
        for (int i = tid; i < 16 * 260; i += 256) o_sh[i] = o[(size_t)e0 * 260 + i];
        for (int i = tid; i < 1600; i += 256) g_sh[i] = g[(size_t)e0 * 100 + i];
        __syncthreads();

        for (int idx = tid; idx < 800; idx += 256) {
            int e = idx / 50, j = idx % 50;
            float acc = bc[j];
            #pragma unroll 4
            for (int k = 0; k < 100; k++)
                acc = fmaf(g_sh[e * 100 + k], __ldg(Wc + k * 50 + j), acc);
            att[e * 52 + j] = 1.0f / (1.0f + expf(-acc));
        }
        __syncthreads();

        for (int idx = tid; idx < 4096; idx += 256) {
            int row = idx >> 5, kp = idx & 31;
            int e = row >> 3, n = row & 7;
            float v[2];
            #pragma unroll
            for (int t = 0; t < 2; t++) {
                int d = kp * 2 + t;
                float x = 0.f;
                if (d < 50) {
                    int gi;
                    if (d < 10)       gi = d;
                    else if (d < 20)  gi = 120 + d;
                    else if (d < 35)  gi = 15 * n + d - 10;
                    else              gi = 15 * n + d + 105;
                    x = o_sh[e * 260 + gi] * att[e * 52 + d];
                }
                v[t] = x;
            }
            *(unsigned*)(smem + OFF_A0 + (unsigned)(row * 72 + kp * 2) * 2) =
                pack_h2(v[0], v[1]);
        }
    }
    __syncthreads();

    for (int q = tid; q < 1152; q += 256)
        CP16(sbase + OFF_R + q * 16, (const char*)W0g + 18432 + q * 16);
    CP_COMMIT();
    for (int q = tid; q < 1320; q += 256)
        CP16(sbase + OFF_R + RS + q * 16, (const char*)W1g + q * 16);
    CP_COMMIT();

    const unsigned aoffA = (unsigned)(((warp * 16 + (lane & 15)) * 72 + ((lane & 16) >> 1)) * 2);
    const int bg = lane >> 3;
    const unsigned brow0 = (unsigned)((bg >> 1) * 8 + (lane & 7));
    const unsigned bk0   = (unsigned)((bg & 1) * 16);
    const unsigned boff1 = (unsigned)(brow0 * 528 + bk0);
    const unsigned boffS = (unsigned)((32 + (lane & 7)) * 528 + ((lane >> 3) & 1) * 16);

    unsigned aA0[4][4];
    #pragma unroll
    for (int s = 0; s < 4; s++)
        ldsm_x4(sbase + OFF_A0 + aoffA + s * 32,
                aA0[s][0], aA0[s][1], aA0[s][2], aA0[s][3]);

    unsigned aH1[16][4];

    // ---- GEMM1 ----
    #pragma unroll
    for (int p = 0; p < 2; p++) {
        if (p == 0) CP_WAIT2(); else CP_WAIT1();
        __syncthreads();
        if (p == 1) {
            for (int q = tid; q < 1320; q += 256)
                CP16(sbase + OFF_R + 2 * RS + q * 16, (const char*)W1g + 21120 + q * 16);
            CP_COMMIT();
        }
        const unsigned base = sbase + OFF_R + (p == 0 ? 2 * RS : 0);
        #pragma unroll
        for (int cc = 0; cc < 2; cc++) {
            const int c = p * 2 + cc;
            float d[8][4];
            #pragma unroll
            for (int t = 0; t < 8; t++)
                #pragma unroll
                for (int i = 0; i < 4; i++) d[t][i] = 0.f;

            #pragma unroll
            for (int s = 0; s < 4; s++) {
                unsigned bh[4][4];
                #pragma unroll
                for (int pr = 0; pr < 4; pr++) {
                    unsigned bo = (unsigned)((cc * 64 + pr * 16 + brow0) * 144) + bk0 + s * 32;
                    ldsm_x4(base + bo, bh[pr][0], bh[pr][1], bh[pr][2], bh[pr][3]);
                }
                #pragma unroll
                for (int pr = 0; pr < 4; pr++) {
                    mma16816(d[2 * pr],     aA0[s][0], aA0[s][1], aA0[s][2], aA0[s][3],
                             bh[pr][0], bh[pr][1]);
                    mma16816(d[2 * pr + 1], aA0[s][0], aA0[s][1], aA0[s][2], aA0[s][3],
                             bh[pr][2], bh[pr][3]);
                }
            }

            #pragma unroll
            for (int u = 0; u < 4; u++) {
                const int s = 4 * c + u;
                int j0 = 64 * c + 16 * u + 2 * (lane & 3);
                int j1 = j0 + 8;
                float b00 = ba0_sh[j0], b01 = ba0_sh[j0 + 1];
                float b10 = ba0_sh[j1], b11 = ba0_sh[j1 + 1];
                aH1[s][0] = pack_h2(fmaxf(d[2*u][0] + b00, 0.f), fmaxf(d[2*u][1] + b01, 0.f));
                aH1[s][1] = pack_h2(fmaxf(d[2*u][2] + b00, 0.f), fmaxf(d[2*u][3] + b01, 0.f));
                aH1[s][2] = pack_h2(fmaxf(d[2*u+1][0] + b10, 0.f), fmaxf(d[2*u+1][1] + b11, 0.f));
                aH1[s][3] = pack_h2(fmaxf(d[2*u+1][2] + b10, 0.f), fmaxf(d[2*u+1][3] + b11, 0.f));
            }
        }
    }

    // ---- GEMM2 ----
    for (int c = 0; c < 10; c++) {
        if (c < 9) CP_WAIT1(); else CP_WAIT0();
        __syncthreads();
        if (c + 2 < 10) {
            for (int q = tid; q < 1320; q += 256)
                CP16(sbase + OFF_R + (unsigned)(c % 3) * RS + q * 16,
                     (const char*)W1g + (size_t)(c + 2) * 21120 + q * 16);
            CP_COMMIT();
        }

        const unsigned bufH = sbase + OFF_R + (unsigned)((c + 1) % 3) * RS;
        float d[5][4];
        #pragma unroll
        for (int t = 0; t < 5; t++)
            #pragma unroll
            for (int i = 0; i < 4; i++) d[t][i] = 0.f;

        #pragma unroll
        for (int s = 0; s < 16; s++) {
            unsigned bh0[4], bh1[4], bhS[2];
            ldsm_x4(bufH + boff1 + s * 32, bh0[0], bh0[1], bh0[2], bh0[3]);
            ldsm_x4(bufH + 16 * 528 + boff1 + s * 32, bh1[0], bh1[1], bh1[2], bh1[3]);
            ldsm_x2(bufH + boffS + s * 32, bhS[0], bhS[1]);
            mma16816(d[0], aH1[s][0], aH1[s][1], aH1[s][2], aH1[s][3], bh0[0], bh0[1]);
            mma16816(d[1], aH1[s][0], aH1[s][1], aH1[s][2], aH1[s][3], bh0[2], bh0[3]);
            mma16816(d[2], aH1[s][0], aH1[s][1], aH1[s][2], aH1[s][3], bh1[0], bh1[1]);
            mma16816(d[3], aH1[s][0], aH1[s][1], aH1[s][2], aH1[s][3], bh1[2], bh1[3]);
            mma16816(d[4], aH1[s][0], aH1[s][1], aH1[s][2], aH1[s][3], bhS[0], bhS[1]);
        }

        #pragma unroll
        for (int t = 0; t < 5; t++) {
            int c0 = c * 40 + t * 8 + (lane & 3) * 2;
            float b0 = ba1_sh[c0], b1 = ba1_sh[c0 + 1];
            float s00 = redsum8(fmaxf(d[t][0] + b0, 0.f));
            float s01 = redsum8(fmaxf(d[t][1] + b1, 0.f));
            float s10 = redsum8(fmaxf(d[t][2] + b0, 0.f));
            float s11 = redsum8(fmaxf(d[t][3] + b1, 0.f));
            if (lane < 4)
                *(unsigned*)&g_iph[(size_t)(e0 + 2 * warp) * 400 + c0] = pack_h2(s00, s01);
            else if (lane < 8)
                *(unsigned*)&g_iph[(size_t)(e0 + 2 * warp + 1) * 400 + c0] = pack_h2(s10, s11);
        }
    }
}

// ===========================================================================
// Kernel 2: policy head v2 — 512 threads / 16 warps, warp (s,h): strip s,
// N-half h. p/q pass between layers via fp16 smem tiles (reuse A0 region).
// 2-slot weight ring, depth-1 prefetch.
// ===========================================================================
#define HRS2     52224          // ring slot (Wp0 chunk 64 x 816)
#define HOFF_A0  0              // ip tile 128x816; later p/q tile 128x528
#define HOFF_W   104448         // 2 slots -> 208896
#define HOFF_W2  208896         // 8 x 528
#define HOFF_BP0 213120
#define HOFF_BP1 214144
#define HOFF_BP2 215168
#define SMEM_HEAD 215200

__global__ __launch_bounds__(512, 1)
void k_head(const float* __restrict__ bp0, const float* __restrict__ bp1,
            const float* __restrict__ bp2, float* __restrict__ out)
{
    extern __shared__ __align__(1024) unsigned char smem[];
    const unsigned sbase = smem_u32(smem);
    const int tid = threadIdx.x, lane = tid & 31, warp = tid >> 5;
    const int s = warp & 7, h = warp >> 3;
    const int e0 = blockIdx.x * 128;

    // ---- G1: A0 (ip fp16, pitch 408h=816B) + Wp2 ----
    for (int q = tid; q < 6400; q += 512) {
        int row = q / 50, col = q % 50;
        CP16(sbase + HOFF_A0 + (unsigned)(row * 816 + col * 16),
             (const char*)(g_iph + (size_t)(e0 + row) * 400) + col * 16);
    }
    for (int q = tid; q < 264; q += 512)
        CP16(sbase + HOFF_W2 + q * 16, (const char*)Wp2g + q * 16);
    CP_COMMIT();
    // ---- G2: Wp0 chunk 0 -> slot 0 ----
    for (int q = tid; q < 3200; q += 512) {
        int row = q / 50, col = q % 50;
        CP16(sbase + HOFF_W + (unsigned)(row * 816 + col * 16),
             (const char*)Wp0g + (size_t)row * 816 + col * 16);
    }
    CP_COMMIT();

    // ---- biases ----
    float* bp0_sh = (float*)(smem + HOFF_BP0);
    float* bp1_sh = (float*)(smem + HOFF_BP1);
    float* bp2_sh = (float*)(smem + HOFF_BP2);
    if (tid < 256) { bp0_sh[tid] = bp0[tid]; bp1_sh[tid] = bp1[tid]; }
    if (tid < 8) bp2_sh[tid] = bp2[tid];

    // per-lane ldmatrix address components
    const unsigned aoffA = (unsigned)((s * 16 + (lane & 15)) * 816 + ((lane & 16) >> 1) * 2);
    const unsigned aoffP = (unsigned)((s * 16 + (lane & 15)) * 528 + ((lane & 16) >> 1) * 2);
    const int bg = lane >> 3;
    const unsigned brow = (unsigned)((bg >> 1) * 8 + (lane & 7));
    const unsigned bk   = (unsigned)((bg & 1) * 16);
    const unsigned boffS = (unsigned)((lane & 7) * 528 + ((lane >> 3) & 1) * 16);

    CP_WAIT0();        // A0 + Wp2 + Wp0 chunk0 all resident
    __syncthreads();

    unsigned aP1[8][4];

    // ================= p0: p = relu(ip @ Wp0 + bp0) =================
    // 4 n-chunks of 64; warp (s,h) handles cols [64c+32h, +32) = 4 n8-tiles.
    for (int c = 0; c < 4; c++) {
        if (c > 0) { CP_WAIT0(); __syncthreads(); }
        if (c + 1 < 4) {       // Wp0 chunk c+1 -> slot (c+1)&1
            for (int q = tid; q < 3200; q += 512) {
                int row = q / 50, col = q % 50;
                CP16(sbase + HOFF_W + (unsigned)(((c + 1) & 1) * HRS2 + row * 816 + col * 16),
                     (const char*)Wp0g + (size_t)((c + 1) * 64 + row) * 816 + col * 16);
            }
            CP_COMMIT();
        } else {               // Wp1 chunk 0 -> slot 0 (read at c=2, done)
            for (int q = tid; q < 2048; q += 512) {
                int row = q >> 5, col = q & 31;
                CP16(sbase + HOFF_W + (unsigned)(row * 528 + col * 16),
                     (const char*)Wp1g + (size_t)row * 528 + col * 16);
            }
            CP_COMMIT();
        }

        const unsigned bufW = sbase + HOFF_W + (unsigned)((c & 1) * HRS2);
        float d[4][4];
        #pragma unroll
        for (int t = 0; t < 4; t++)
            #pragma unroll
            for (int i = 0; i < 4; i++) d[t][i] = 0.f;

        #pragma unroll
        for (int s25 = 0; s25 < 25; s25++) {
            unsigned a[4];
            ldsm_x4(sbase + HOFF_A0 + aoffA + s25 * 32, a[0], a[1], a[2], a[3]);
            #pragma unroll
            for (int pr = 0; pr < 2; pr++) {
                unsigned b[4];
                unsigned bo = (unsigned)((32 * h + pr * 16 + brow) * 816) + bk + s25 * 32;
                ldsm_x4(bufW + bo, b[0], b[1], b[2], b[3]);
                mma16816(d[2 * pr],     a[0], a[1], a[2], a[3], b[0], b[1]);
                mma16816(d[2 * pr + 1], a[0], a[1], a[2], a[3], b[2], b[3]);
            }
        }

        // epilogue: bias + relu + pack -> k-slices 4c + 2h + u
        #pragma unroll
        for (int u = 0; u < 2; u++) {
            int j0 = 64 * c + 32 * h + 16 * u + 2 * (lane & 3);
            int j1 = j0 + 8;
            float b00 = bp0_sh[j0], b01 = bp0_sh[j0 + 1];
            float b10 = bp0_sh[j1], b11 = bp0_sh[j1 + 1];
            aP1[2*c+u][0] = pack_h2(fmaxf(d[2*u][0] + b00, 0.f), fmaxf(d[2*u][1] + b01, 0.f));
            aP1[2*c+u][1] = pack_h2(fmaxf(d[2*u][2] + b00, 0.f), fmaxf(d[2*u][3] + b01, 0.f));
            aP1[2*c+u][2] = pack_h2(fmaxf(d[2*u+1][0] + b10, 0.f), fmaxf(d[2*u+1][1] + b11, 0.f));
            aP1[2*c+u][3] = pack_h2(fmaxf(d[2*u+1][2] + b10, 0.f), fmaxf(d[2*u+1][3] + b11, 0.f));
        }
    }
    __syncthreads();   // all A0 / last-slot reads done

    // ---- write p-tile (fp16, pitch 528B) over A0 region ----
    {
        int r = lane >> 2, c2 = 2 * (lane & 3);
        #pragma unroll
        for (int i = 0; i < 8; i++) {
            int S = 4 * (i >> 1) + 2 * h + (i & 1);
            unsigned base = sbase + HOFF_A0 +
                (unsigned)((16 * s + r) * 528 + (16 * S + c2) * 2);
            sts32(base,                aP1[i][0]);
            sts32(base + 16,           aP1[i][2]);
            sts32(base + 8 * 528,      aP1[i][1]);
            sts32(base + 8 * 528 + 16, aP1[i][3]);
        }
    }
    CP_WAIT0();        // Wp1 chunk 0 resident
    __syncthreads();   // p-tile visible

    unsigned aQ[8][4];

    // ================= p1: q = relu(p @ Wp1 + bp1) =================
    for (int c = 0; c < 4; c++) {
        if (c > 0) { CP_WAIT0(); __syncthreads(); }
        if (c + 1 < 4) {       // Wp1 chunk c+1 -> slot (c+1)&1
            for (int q = tid; q < 2048; q += 512) {
                int row = q >> 5, col = q & 31;
                CP16(sbase + HOFF_W + (unsigned)(((c + 1) & 1) * HRS2 + row * 528 + col * 16),
                     (const char*)Wp1g + (size_t)((c + 1) * 64 + row) * 528 + col * 16);
            }
            CP_COMMIT();
        }

        const unsigned bufW = sbase + HOFF_W + (unsigned)((c & 1) * HRS2);
        float d[4][4];
        #pragma unroll
        for (int t = 0; t < 4; t++)
            #pragma unroll
            for (int i = 0; i < 4; i++) d[t][i] = 0.f;

        #pragma unroll
        for (int s16 = 0; s16 < 16; s16++) {
            unsigned a[4];
            ldsm_x4(sbase + HOFF_A0 + aoffP + s16 * 32, a[0], a[1], a[2], a[3]);
            #pragma unroll
            for (int pr = 0; pr < 2; pr++) {
                unsigned b[4];
                unsigned bo = (unsigned)((32 * h + pr * 16 + brow) * 528) + bk + s16 * 32;
                ldsm_x4(bufW + bo, b[0], b[1], b[2], b[3]);
                mma16816(d[2 * pr],     a[0], a[1], a[2], a[3], b[0], b[1]);
                mma16816(d[2 * pr + 1], a[0], a[1], a[2], a[3], b[2], b[3]);
            }
        }

        #pragma unroll
        for (int u = 0; u < 2; u++) {
            int j0 = 64 * c + 32 * h + 16 * u + 2 * (lane & 3);
            int j1 = j0 + 8;
            float b00 = bp1_sh[j0], b01 = bp1_sh[j0 + 1];
            float b10 = bp1_sh[j1], b11 = bp1_sh[j1 + 1];
            aQ[2*c+u][0] = pack_h2(fmaxf(d[2*u][0] + b00, 0.f), fmaxf(d[2*u][1] + b01, 0.f));
            aQ[2*c+u][1] = pack_h2(fmaxf(d[2*u][2] + b00, 0.f), fmaxf(d[2*u][3] + b01, 0.f));
            aQ[2*c+u][2] = pack_h2(fmaxf(d[2*u+1][0] + b10, 0.f), fmaxf(d[2*u+1][1] + b11, 0.f));
            aQ[2*c+u][3] = pack_h2(fmaxf(d[2*u+1][2] + b10, 0.f), fmaxf(d[2*u+1][3] + b11, 0.f));
        }
    }
    __syncthreads();   // p-tile reads done

    // ---- write q-tile (overwrites p-tile) ----
    {
        int r = lane >> 2, c2 = 2 * (lane & 3);
        #pragma unroll
        for (int i = 0; i < 8; i++) {
            int S = 4 * (i >> 1) + 2 * h + (i & 1);
            unsigned base = sbase + HOFF_A0 +
                (unsigned)((16 * s + r) * 528 + (16 * S + c2) * 2);
            sts32(base,                aQ[i][0]);
            sts32(base + 16,           aQ[i][2]);
            sts32(base + 8 * 528,      aQ[i][1]);
            sts32(base + 8 * 528 + 16, aQ[i][3]);
        }
    }
    __syncthreads();   // q-tile visible

    // ================= p2: out = tanh(q @ Wp2 + bp2), h==0 warps =================
    if (h == 0) {
        const unsigned w2 = sbase + HOFF_W2;
        float d2[4] = {0.f, 0.f, 0.f, 0.f};
        #pragma unroll
        for (int s16 = 0; s16 < 16; s16++) {
            unsigned a[4], b0, b1;
            ldsm_x4(sbase + HOFF_A0 + aoffP + s16 * 32, a[0], a[1], a[2], a[3]);
            ldsm_x2(w2 + boffS + s16 * 32, b0, b1);
            mma16816(d2, a[0], a[1], a[2], a[3], b0, b1);
        }
        int row = lane >> 2, col = 2 * (lane & 3);
        float bb0 = bp2_sh[col], bb1 = bp2_sh[col + 1];
        int elo = e0 + s * 16 + row;
        *(float2*)&out[(size_t)elo * 8 + col] =
            make_float2(tanhf(d2[0] + bb0), tanhf(d2[1] + bb1));
        *(float2*)&out[(size_t)(elo + 8) * 8 + col] =
            make_float2(tanhf(d2[2] + bb0), tanhf(d2[3] + bb1));
    }
}

// ===========================================================================
extern "C" void kernel_launch(void* const* d_in, const int* in_sizes, int n_in,
                              void* d_out, int out_size)
{
    const float* o   = (const float*)d_in[0];
    const float* g   = (const float*)d_in[1];
    const float* Wc  = (const float*)d_in[2];
    const float* bc  = (const float*)d_in[3];
    const float* Wa0 = (const float*)d_in[4];
    const float* ba0 = (const float*)d_in[5];
    const float* Wa1 = (const float*)d_in[6];
    const float* ba1 = (const float*)d_in[7];
    const float* Wp0 = (const float*)d_in[8];
    const float* bp0 = (const float*)d_in[9];
    const float* Wp1 = (const float*)d_in[10];
    const float* bp1 = (const float*)d_in[11];
    const float* Wp2 = (const float*)d_in[12];
    const float* bp2 = (const float*)d_in[13];
    float* out = (float*)d_out;

    int B = in_sizes[0] / 260;

    cudaFuncSetAttribute(k_main, cudaFuncAttributeMaxDynamicSharedMemorySize, SMEM_MAIN);
    cudaFuncSetAttribute(k_head, cudaFuncAttributeMaxDynamicSharedMemorySize, SMEM_HEAD);

    k_prep<<<1128, 256>>>(Wa0, Wa1, Wp0, Wp1, Wp2);
    k_main<<<B / 16, 256, SMEM_MAIN>>>(o, g, Wc, bc, ba0, ba1);
    k_head<<<B / 128, 512, SMEM_HEAD>>>(bp0, bp1, bp2, out);
}